// round 10
// baseline (speedup 1.0000x reference)
#include <cuda_runtime.h>
#include <math.h>

// Problem constants
#define NTOKS 4096   // B*T
#define DIMV  512
#define QDV   2048   // 2*H*DH
#define HV    8
#define DHV   128
#define NKV   256
#define KKV   16

typedef unsigned long long ull;

// packed fp32x2 FMA (sm_103a FFMA2) — bit-exact fp32 per lane
#define FMA2(d, a, b) \
    asm("fma.rn.f32x2 %0, %1, %2, %0;" : "+l"(d) : "l"(a), "l"(b))
#define PACKDUP(out, x) \
    asm("mov.b64 %0, {%1, %1};" : "=l"(out) : "r"(__float_as_uint(x)))
#define UNPACK2(lo, hi, in) \
    asm("mov.b64 {%0, %1}, %2;" : "=r"(lo), "=r"(hi) : "l"(in))

// Scratch (allocation-free rule: __device__ globals)
__device__ __align__(16) float g_q[NTOKS * QDV];          // projected then LN'd q
__device__ __align__(16) float g_attn[NTOKS * HV * KKV];  // softmax weights
__device__ __align__(16) int   g_vidx[NTOKS * HV * KKV];  // value row indices

// Stage-2 candidate tables: (i,j) with (i+1)(j+1) <= 16 — 50 candidates,
// provably a superset of the top-16 of sx[i]+sy[j] with sx,sy sorted desc
// (exact under the reference's lower-flattened-index tie-break).
__device__ __constant__ int c_ci[64] = {
    0,0,0,0,0,0,0,0,0,0,0,0,0,0,0,0,
    1,1,1,1,1,1,1,1,
    2,2,2,2,2,
    3,3,3,3,
    4,4,4,
    5,5, 6,6, 7,7,
    8,9,10,11,12,13,14,15,
    0,0,0,0,0,0,0,0,0,0,0,0,0,0};
__device__ __constant__ int c_cj[64] = {
    0,1,2,3,4,5,6,7,8,9,10,11,12,13,14,15,
    0,1,2,3,4,5,6,7,
    0,1,2,3,4,
    0,1,2,3,
    0,1,2,
    0,1, 0,1, 0,1,
    0,0,0,0,0,0,0,0,
    0,0,0,0,0,0,0,0,0,0,0,0,0,0};

// ---------------------------------------------------------------------------
// K1: q = x @ Wq^T  (M=4096, N=2048, K=512), FFMA2, bit-exact sequential-k
// chain per output. Double-buffered smem + register prefetch: ONE sync per
// 16-k tile; LDG(t+1) and STS(t+1) retire under compute(t).
// ---------------------------------------------------------------------------
__global__ __launch_bounds__(256) void k1_gemm(const float* __restrict__ X,
                                               const float* __restrict__ W)
{
    __shared__ float As[2][16][68];    // [buf][k][m]
    __shared__ float Bs[2][16][132];   // [buf][k][n]

    const int tid = threadIdx.x;
    const int tx = tid & 31;       // n-group: cols tx*4..tx*4+3
    const int ty = tid >> 5;       // m-group (warp id)
    const int m0 = blockIdx.x * 64;
    const int n0 = blockIdx.y * 128;

    ull acc[4][4];                 // [row-pair][col]
#pragma unroll
    for (int ip = 0; ip < 4; ip++)
#pragma unroll
        for (int j = 0; j < 4; j++) acc[ip][j] = 0ULL;

    const int arow = tid >> 2;          // 0..63
    const int akc  = (tid & 3) << 2;    // 0,4,8,12
    const int brow0 = tid >> 2;         // 0..63   (q=0)
    const int brow1 = 64 + (tid >> 2);  // 64..127 (q=1)

    const float* Abase = X + (size_t)(m0 + arow) * DIMV + akc;
    const float* Bbase0 = W + (size_t)(n0 + brow0) * DIMV + akc;
    const float* Bbase1 = W + (size_t)(n0 + brow1) * DIMV + akc;

    // prologue: stage tile kt=0 into buf 0
    float4 pa  = *(const float4*)(Abase);
    float4 pb0 = *(const float4*)(Bbase0);
    float4 pb1 = *(const float4*)(Bbase1);
    As[0][akc + 0][arow] = pa.x; As[0][akc + 1][arow] = pa.y;
    As[0][akc + 2][arow] = pa.z; As[0][akc + 3][arow] = pa.w;
    Bs[0][akc + 0][brow0] = pb0.x; Bs[0][akc + 1][brow0] = pb0.y;
    Bs[0][akc + 2][brow0] = pb0.z; Bs[0][akc + 3][brow0] = pb0.w;
    Bs[0][akc + 0][brow1] = pb1.x; Bs[0][akc + 1][brow1] = pb1.y;
    Bs[0][akc + 2][brow1] = pb1.z; Bs[0][akc + 3][brow1] = pb1.w;
    __syncthreads();

    int cur = 0;
    for (int kt = 0; kt < DIMV; kt += 16) {
        const bool more = (kt + 16 < DIMV);
        if (more) {
            pa  = *(const float4*)(Abase + kt + 16);
            pb0 = *(const float4*)(Bbase0 + kt + 16);
            pb1 = *(const float4*)(Bbase1 + kt + 16);
        }
#pragma unroll 4
        for (int k = 0; k < 16; k++) {
            ulonglong2 a01 = *(const ulonglong2*)&As[cur][k][ty * 4];
            ulonglong2 a23 = *(const ulonglong2*)&As[cur][k][32 + ty * 4];
            ull av[4] = {a01.x, a01.y, a23.x, a23.y};
            float4 b = *(const float4*)&Bs[cur][k][tx * 4];
            ull bd[4];
            PACKDUP(bd[0], b.x); PACKDUP(bd[1], b.y);
            PACKDUP(bd[2], b.z); PACKDUP(bd[3], b.w);
#pragma unroll
            for (int ip = 0; ip < 4; ip++)
#pragma unroll
                for (int j = 0; j < 4; j++)
                    FMA2(acc[ip][j], av[ip], bd[j]);
        }
        if (more) {
            int nxt = cur ^ 1;
            As[nxt][akc + 0][arow] = pa.x; As[nxt][akc + 1][arow] = pa.y;
            As[nxt][akc + 2][arow] = pa.z; As[nxt][akc + 3][arow] = pa.w;
            Bs[nxt][akc + 0][brow0] = pb0.x; Bs[nxt][akc + 1][brow0] = pb0.y;
            Bs[nxt][akc + 2][brow0] = pb0.z; Bs[nxt][akc + 3][brow0] = pb0.w;
            Bs[nxt][akc + 0][brow1] = pb1.x; Bs[nxt][akc + 1][brow1] = pb1.y;
            Bs[nxt][akc + 2][brow1] = pb1.z; Bs[nxt][akc + 3][brow1] = pb1.w;
            __syncthreads();
            cur = nxt;
        }
    }

    // store: row = (ip>>1)*32 + ty*4 + (ip&1)*2 + e, cols n0 + tx*4 + j
#pragma unroll
    for (int ip = 0; ip < 4; ip++) {
#pragma unroll
        for (int e = 0; e < 2; e++) {
            int row = (ip >> 1) * 32 + ty * 4 + (ip & 1) * 2 + e;
            float o[4];
#pragma unroll
            for (int j = 0; j < 4; j++) {
                unsigned lo, hi;
                UNPACK2(lo, hi, acc[ip][j]);
                o[j] = __uint_as_float(e ? hi : lo);
            }
            float* dst = g_q + (size_t)(m0 + row) * QDV + n0 + tx * 4;
            *(float4*)dst = make_float4(o[0], o[1], o[2], o[3]);
        }
    }
}

// ---------------------------------------------------------------------------
// K2: LayerNorm over each 128-elem subrow of g_q (in place). Warp per row.
// VERBATIM round-2 kernel (bit-exact reduction tree).
// ---------------------------------------------------------------------------
__global__ __launch_bounds__(256) void k2_ln(const float* __restrict__ gamma,
                                             const float* __restrict__ beta)
{
    int gw = (int)((blockIdx.x * blockDim.x + threadIdx.x) >> 5);  // 0..65535
    int lane = threadIdx.x & 31;
    float* row = g_q + (size_t)gw * DHV;

    float4 v = *(float4*)(row + lane * 4);
    float s = v.x + v.y + v.z + v.w;
#pragma unroll
    for (int o = 16; o; o >>= 1) s += __shfl_xor_sync(0xffffffffu, s, o);
    float mu = s * (1.0f / 128.0f);

    float dx = v.x - mu, dy = v.y - mu, dz = v.z - mu, dw = v.w - mu;
    float ss = dx * dx + dy * dy + dz * dz + dw * dw;
#pragma unroll
    for (int o = 16; o; o >>= 1) ss += __shfl_xor_sync(0xffffffffu, ss, o);
    float inv = rsqrtf(ss * (1.0f / 128.0f) + 1e-5f);

    float4 g4 = *(const float4*)(gamma + lane * 4);
    float4 b4 = *(const float4*)(beta + lane * 4);
    v.x = dx * inv * g4.x + b4.x;
    v.y = dy * inv * g4.y + b4.y;
    v.z = dz * inv * g4.z + b4.z;
    v.w = dw * inv * g4.w + b4.w;
    *(float4*)(row + lane * 4) = v;
}

// ---------------------------------------------------------------------------
// K3 (fused K4): dots (FFMA2, k-order 0..127 per p — bit-exact) restructured
// into 16 double-buffered 16-k chunks with register prefetch (one sync per
// chunk); selection phase verbatim from round 9 (ILP-2 stage-1, pruned
// stage-2, softmax).
// ---------------------------------------------------------------------------
__global__ __launch_bounds__(256) void k3_fused(const float* __restrict__ keys)
{
    __shared__ float qs[2][32][34];   // [buf][token][k(16)+pad]
    __shared__ float ks[2][16][256];  // [buf][k][key]

    const int tid = threadIdx.x;
    const int tx = tid & 31;
    const int wy = tid >> 5;       // warp id: token group
    const int tt = blockIdx.x;
    const int h = blockIdx.y;
    const int t0 = tt * 32;

    ull acc[2][4][4];              // [p][token][key-pair-quad]
#pragma unroll
    for (int p = 0; p < 2; p++)
#pragma unroll
        for (int i = 0; i < 4; i++)
#pragma unroll
            for (int jq = 0; jq < 4; jq++) acc[p][i][jq] = 0ULL;

    const int tl = tid >> 3;            // 0..31 token for q staging
    const int kc = (tid & 7) << 1;      // 0..14 (float2)

    const float* qb0 = g_q + (size_t)h * DHV + (size_t)(t0 + tl) * QDV + kc;
    const float* kb0 = keys + ((size_t)(h * NKV + tid) * 2) * DHV;

    // chunk c (0..15): p = c>>3, kt = (c&7)*16
    // prologue: stage chunk 0 into buf 0
    {
        float2 q2 = *(const float2*)(qb0);
        *(float2*)&qs[0][tl][kc] = q2;
        const float* kr = kb0;  // p=0, kt=0
#pragma unroll
        for (int c2 = 0; c2 < 4; c2++) {
            float4 k4 = *(const float4*)(kr + c2 * 4);
            ks[0][c2 * 4 + 0][tid] = k4.x; ks[0][c2 * 4 + 1][tid] = k4.y;
            ks[0][c2 * 4 + 2][tid] = k4.z; ks[0][c2 * 4 + 3][tid] = k4.w;
        }
    }
    __syncthreads();

    int cur = 0;
#pragma unroll 1
    for (int c = 0; c < 16; c++) {
        const bool more = (c + 1 < 16);
        float2 pq;
        float4 pk[4];
        if (more) {
            int pn = (c + 1) >> 3;
            int ktn = ((c + 1) & 7) * 16;
            pq = *(const float2*)(qb0 + (size_t)pn * HV * DHV + ktn);
            const float* kr = kb0 + (size_t)pn * DHV + ktn;
#pragma unroll
            for (int c2 = 0; c2 < 4; c2++)
                pk[c2] = *(const float4*)(kr + c2 * 4);
        }

        const int pcur = c >> 3;
#pragma unroll 4
        for (int k = 0; k < 16; k++) {
            ull kv[4];
#pragma unroll
            for (int jq = 0; jq < 4; jq++)
                kv[jq] = *(const ull*)&ks[cur][k][64 * jq + 2 * tx];
#pragma unroll
            for (int i = 0; i < 4; i++) {
                ull qd;
                PACKDUP(qd, qs[cur][wy + 8 * i][k]);
#pragma unroll
                for (int jq = 0; jq < 4; jq++)
                    FMA2(acc[pcur][i][jq], qd, kv[jq]);
            }
        }

        if (more) {
            int nxt = cur ^ 1;
            *(float2*)&qs[nxt][tl][kc] = pq;
#pragma unroll
            for (int c2 = 0; c2 < 4; c2++) {
                ks[nxt][c2 * 4 + 0][tid] = pk[c2].x;
                ks[nxt][c2 * 4 + 1][tid] = pk[c2].y;
                ks[nxt][c2 * 4 + 2][tid] = pk[c2].z;
                ks[nxt][c2 * 4 + 3][tid] = pk[c2].w;
            }
            __syncthreads();
            cur = nxt;
        }
    }

    // selection per token (verbatim round 9)
#pragma unroll 1
    for (int i = 0; i < 4; i++) {
        const int t = t0 + wy + 8 * i;
        float s1s[2];
        int s1i[2];

        // stage 1: top-16 of 256 for BOTH p, interleaved (ILP-2)
        float v0[8], v1[8];
#pragma unroll
        for (int jq = 0; jq < 4; jq++) {
            unsigned lo, hi;
            UNPACK2(lo, hi, acc[0][i][jq]);
            v0[2 * jq + 0] = __uint_as_float(lo);
            v0[2 * jq + 1] = __uint_as_float(hi);
            UNPACK2(lo, hi, acc[1][i][jq]);
            v1[2 * jq + 0] = __uint_as_float(lo);
            v1[2 * jq + 1] = __uint_as_float(hi);
        }
        float os0 = 0.f, os1 = 0.f; int oi0 = 0, oi1 = 0;
#pragma unroll 1
        for (int it = 0; it < 16; it++) {
            float bv0 = -INFINITY, bv1 = -INFINITY;
            int bi0 = 0x7fffffff, bi1 = 0x7fffffff;
#pragma unroll
            for (int s = 0; s < 8; s++) {
                int n = ((s >> 1) << 6) + 2 * tx + (s & 1);
                if (v0[s] > bv0) { bv0 = v0[s]; bi0 = n; }
                if (v1[s] > bv1) { bv1 = v1[s]; bi1 = n; }
            }
#pragma unroll
            for (int o = 16; o; o >>= 1) {
                float ov0 = __shfl_xor_sync(0xffffffffu, bv0, o);
                int   on0 = __shfl_xor_sync(0xffffffffu, bi0, o);
                float ov1 = __shfl_xor_sync(0xffffffffu, bv1, o);
                int   on1 = __shfl_xor_sync(0xffffffffu, bi1, o);
                if (ov0 > bv0 || (ov0 == bv0 && on0 < bi0)) { bv0 = ov0; bi0 = on0; }
                if (ov1 > bv1 || (ov1 == bv1 && on1 < bi1)) { bv1 = ov1; bi1 = on1; }
            }
            if (tx == it) { os0 = bv0; oi0 = bi0; os1 = bv1; oi1 = bi1; }
            if (((bi0 >> 1) & 31) == tx) {
                int sl = ((bi0 >> 6) << 1) | (bi0 & 1);
                v0[sl] = -INFINITY;
            }
            if (((bi1 >> 1) & 31) == tx) {
                int sl = ((bi1 >> 6) << 1) | (bi1 & 1);
                v1[sl] = -INFINITY;
            }
        }
        s1s[0] = os0; s1i[0] = oi0;
        s1s[1] = os1; s1i[1] = oi1;

        // stage 2: top-16 of 50 pruned candidates (lane l: c=l and c=l+32)
        float v2[2]; int cc2[2];
#pragma unroll
        for (int e = 0; e < 2; e++) {
            int c = tx + 32 * e;
            int ii = c_ci[c], jj = c_cj[c];
            float sxv = __shfl_sync(0xffffffffu, s1s[0], ii);
            float syv = __shfl_sync(0xffffffffu, s1s[1], jj);
            v2[e] = (c < 50) ? sxv + syv : -INFINITY;
            cc2[e] = ii * 16 + jj;
        }
        float os = 0.f; int occ = 0;
#pragma unroll 1
        for (int it = 0; it < 16; it++) {
            float bv = -INFINITY; int bcc = 0x7fffffff;
#pragma unroll
            for (int e = 0; e < 2; e++)
                if (v2[e] > bv || (v2[e] == bv && cc2[e] < bcc)) { bv = v2[e]; bcc = cc2[e]; }
#pragma unroll
            for (int o = 16; o; o >>= 1) {
                float ov = __shfl_xor_sync(0xffffffffu, bv, o);
                int oc2 = __shfl_xor_sync(0xffffffffu, bcc, o);
                if (ov > bv || (ov == bv && oc2 < bcc)) { bv = ov; bcc = oc2; }
            }
            if (tx == it) { os = bv; occ = bcc; }
#pragma unroll
            for (int e = 0; e < 2; e++)
                if (cc2[e] == bcc) v2[e] = -INFINITY;
        }

        // softmax over 16 selected (lane 0 = max) + index gather
        float mx = __shfl_sync(0xffffffffu, os, 0);
        float ev = (tx < 16) ? expf(os - mx) : 0.f;
        float sum = ev;
#pragma unroll
        for (int o = 16; o; o >>= 1) sum += __shfl_xor_sync(0xffffffffu, sum, o);
        int ix = __shfl_sync(0xffffffffu, s1i[0], (occ >> 4) & 15);
        int iy = __shfl_sync(0xffffffffu, s1i[1], occ & 15);
        if (tx < 16) {
            int o = (t * HV + h) * KKV + tx;
            g_attn[o] = ev / sum;
            g_vidx[o] = ix * NKV + iy;
        }
    }
}

// ---------------------------------------------------------------------------
// K5: out[t,:] = sum_{m<128} attn[t,m] * values[vidx[t,m], :]
// (at DRAM/L2 bandwidth floor per ncu — unchanged)
// ---------------------------------------------------------------------------
__global__ __launch_bounds__(128) void k5_out(const float* __restrict__ values,
                                              float* __restrict__ out)
{
    __shared__ float sa[128];
    __shared__ int   sv[128];
    const int t = blockIdx.x;
    const int tid = threadIdx.x;
    sa[tid] = g_attn[(size_t)t * 128 + tid];
    sv[tid] = g_vidx[(size_t)t * 128 + tid];
    __syncthreads();

    const float4* V = (const float4*)values;
    float4 acc = make_float4(0.f, 0.f, 0.f, 0.f);
#pragma unroll 8
    for (int m = 0; m < 128; m++) {
        float a = sa[m];
        float4 vv = V[(size_t)sv[m] * 128 + tid];
        acc.x = fmaf(a, vv.x, acc.x);
        acc.y = fmaf(a, vv.y, acc.y);
        acc.z = fmaf(a, vv.z, acc.z);
        acc.w = fmaf(a, vv.w, acc.w);
    }
    ((float4*)out)[(size_t)t * 128 + tid] = acc;
}

// ---------------------------------------------------------------------------
extern "C" void kernel_launch(void* const* d_in, const int* in_sizes, int n_in,
                              void* d_out, int out_size)
{
    const float* x      = (const float*)d_in[0];  // (4,1024,512)
    const float* Wq     = (const float*)d_in[1];  // (2048,512)
    const float* ln_g   = (const float*)d_in[2];  // (128,)
    const float* ln_b   = (const float*)d_in[3];  // (128,)
    const float* keys   = (const float*)d_in[4];  // (8,256,2,128)
    const float* values = (const float*)d_in[5];  // (65536,512)
    float* out = (float*)d_out;                   // (4,1024,512)

    k1_gemm<<<dim3(NTOKS / 64, QDV / 128), 256>>>(x, Wq);
    k2_ln<<<(NTOKS * 16) / 8, 256>>>(ln_g, ln_b);
    k3_fused<<<dim3(NTOKS / 32, HV), 256>>>(keys);
    k5_out<<<NTOKS, 128>>>(values, out);
}

// round 11
// speedup vs baseline: 1.0949x; 1.0949x over previous
#include <cuda_runtime.h>
#include <math.h>

// Problem constants
#define NTOKS 4096   // B*T
#define DIMV  512
#define QDV   2048   // 2*H*DH
#define HV    8
#define DHV   128
#define NKV   256
#define KKV   16

typedef unsigned long long ull;

// packed fp32x2 FMA (sm_103a FFMA2) — bit-exact fp32 per lane
#define FMA2(d, a, b) \
    asm("fma.rn.f32x2 %0, %1, %2, %0;" : "+l"(d) : "l"(a), "l"(b))
#define PACKDUP(out, x) \
    asm("mov.b64 %0, {%1, %1};" : "=l"(out) : "r"(__float_as_uint(x)))
#define UNPACK2(lo, hi, in) \
    asm("mov.b64 {%0, %1}, %2;" : "=r"(lo), "=r"(hi) : "l"(in))

// Scratch (allocation-free rule: __device__ globals)
__device__ __align__(16) float g_q[NTOKS * QDV];          // LN'd projected q
__device__ __align__(16) float g_attn[NTOKS * HV * KKV];  // softmax weights
__device__ __align__(16) int   g_vidx[NTOKS * HV * KKV];  // value row indices

// Stage-2 candidate tables: (i,j) with (i+1)(j+1) <= 16 — 50 candidates,
// provably a superset of the top-16 of sx[i]+sy[j] with sx,sy sorted desc
// (exact under the reference's lower-flattened-index tie-break).
__device__ __constant__ int c_ci[64] = {
    0,0,0,0,0,0,0,0,0,0,0,0,0,0,0,0,
    1,1,1,1,1,1,1,1,
    2,2,2,2,2,
    3,3,3,3,
    4,4,4,
    5,5, 6,6, 7,7,
    8,9,10,11,12,13,14,15,
    0,0,0,0,0,0,0,0,0,0,0,0,0,0};
__device__ __constant__ int c_cj[64] = {
    0,1,2,3,4,5,6,7,8,9,10,11,12,13,14,15,
    0,1,2,3,4,5,6,7,
    0,1,2,3,4,
    0,1,2,3,
    0,1,2,
    0,1, 0,1, 0,1,
    0,0,0,0,0,0,0,0,
    0,0,0,0,0,0,0,0,0,0,0,0,0,0};

// ---------------------------------------------------------------------------
// K1 (+fused LN): q = LN(x @ Wq^T). GEMM identical to round 9 (single-buffer
// smem + register prefetch, FFMA2, bit-exact sequential-k chain). LN fused in
// the epilogue: each warp owns full 128-col rows with 4 consecutive cols per
// lane — the EXACT layout and reduction tree of the old k2 warp-per-row
// kernel (per-lane x+y+z+w, xor-shuffle 16..1) -> bit-identical q.
// ---------------------------------------------------------------------------
__global__ __launch_bounds__(256) void k1_gemm_ln(const float* __restrict__ X,
                                                  const float* __restrict__ W,
                                                  const float* __restrict__ gamma,
                                                  const float* __restrict__ beta)
{
    __shared__ float As[16][68];    // [k][m] 64 rows + pad
    __shared__ float Bs[16][132];   // [k][n] 128 rows + pad

    const int tid = threadIdx.x;
    const int tx = tid & 31;       // n-group: cols tx*4..tx*4+3
    const int ty = tid >> 5;       // m-group (warp id)
    const int m0 = blockIdx.x * 64;
    const int n0 = blockIdx.y * 128;   // exactly one (p,h) head slice

    ull acc[4][4];                 // [row-pair][col]
#pragma unroll
    for (int ip = 0; ip < 4; ip++)
#pragma unroll
        for (int j = 0; j < 4; j++) acc[ip][j] = 0ULL;

    const int arow = tid >> 2;          // 0..63
    const int akc  = (tid & 3) << 2;    // 0,4,8,12
    const int brow0 = tid >> 2;         // 0..63   (q=0)
    const int brow1 = 64 + (tid >> 2);  // 64..127 (q=1)

    const float* Abase = X + (size_t)(m0 + arow) * DIMV + akc;
    const float* Bbase0 = W + (size_t)(n0 + brow0) * DIMV + akc;
    const float* Bbase1 = W + (size_t)(n0 + brow1) * DIMV + akc;

    // prologue: prefetch tile kt=0
    float4 pa  = *(const float4*)(Abase);
    float4 pb0 = *(const float4*)(Bbase0);
    float4 pb1 = *(const float4*)(Bbase1);

    for (int kt = 0; kt < DIMV; kt += 16) {
        As[akc + 0][arow] = pa.x; As[akc + 1][arow] = pa.y;
        As[akc + 2][arow] = pa.z; As[akc + 3][arow] = pa.w;
        Bs[akc + 0][brow0] = pb0.x; Bs[akc + 1][brow0] = pb0.y;
        Bs[akc + 2][brow0] = pb0.z; Bs[akc + 3][brow0] = pb0.w;
        Bs[akc + 0][brow1] = pb1.x; Bs[akc + 1][brow1] = pb1.y;
        Bs[akc + 2][brow1] = pb1.z; Bs[akc + 3][brow1] = pb1.w;
        __syncthreads();

        if (kt + 16 < DIMV) {
            pa  = *(const float4*)(Abase + kt + 16);
            pb0 = *(const float4*)(Bbase0 + kt + 16);
            pb1 = *(const float4*)(Bbase1 + kt + 16);
        }

#pragma unroll 4
        for (int k = 0; k < 16; k++) {
            ulonglong2 a01 = *(const ulonglong2*)&As[k][ty * 4];
            ulonglong2 a23 = *(const ulonglong2*)&As[k][32 + ty * 4];
            ull av[4] = {a01.x, a01.y, a23.x, a23.y};
            float4 b = *(const float4*)&Bs[k][tx * 4];
            ull bd[4];
            PACKDUP(bd[0], b.x); PACKDUP(bd[1], b.y);
            PACKDUP(bd[2], b.z); PACKDUP(bd[3], b.w);
#pragma unroll
            for (int ip = 0; ip < 4; ip++)
#pragma unroll
                for (int j = 0; j < 4; j++)
                    FMA2(acc[ip][j], av[ip], bd[j]);
        }
        __syncthreads();
    }

    // epilogue: LN per row (EXACT k2 layout: lane tx holds cols tx*4..tx*4+3
    // of a full 128-col row owned by this warp), then store.
    float4 g4 = *(const float4*)(gamma + tx * 4);
    float4 b4 = *(const float4*)(beta + tx * 4);

#pragma unroll
    for (int ip = 0; ip < 4; ip++) {
#pragma unroll
        for (int e = 0; e < 2; e++) {
            int row = (ip >> 1) * 32 + ty * 4 + (ip & 1) * 2 + e;
            float4 v;
            {
                unsigned lo, hi;
                UNPACK2(lo, hi, acc[ip][0]); v.x = __uint_as_float(e ? hi : lo);
                UNPACK2(lo, hi, acc[ip][1]); v.y = __uint_as_float(e ? hi : lo);
                UNPACK2(lo, hi, acc[ip][2]); v.z = __uint_as_float(e ? hi : lo);
                UNPACK2(lo, hi, acc[ip][3]); v.w = __uint_as_float(e ? hi : lo);
            }
            // ---- verbatim k2 arithmetic ----
            float s = v.x + v.y + v.z + v.w;
#pragma unroll
            for (int o = 16; o; o >>= 1) s += __shfl_xor_sync(0xffffffffu, s, o);
            float mu = s * (1.0f / 128.0f);

            float dx = v.x - mu, dy = v.y - mu, dz = v.z - mu, dw = v.w - mu;
            float ss = dx * dx + dy * dy + dz * dz + dw * dw;
#pragma unroll
            for (int o = 16; o; o >>= 1) ss += __shfl_xor_sync(0xffffffffu, ss, o);
            float inv = rsqrtf(ss * (1.0f / 128.0f) + 1e-5f);

            v.x = dx * inv * g4.x + b4.x;
            v.y = dy * inv * g4.y + b4.y;
            v.z = dz * inv * g4.z + b4.z;
            v.w = dw * inv * g4.w + b4.w;
            // ---- end k2 arithmetic ----
            float* dst = g_q + (size_t)(m0 + row) * QDV + n0 + tx * 4;
            *(float4*)dst = v;
        }
    }
}

// ---------------------------------------------------------------------------
// K3 (fused K4): VERBATIM round 9. Dots (FFMA2, bit-exact k-order) + ILP-2
// stage-1 top-16 + pruned stage-2 (50 cands) + softmax.
// ---------------------------------------------------------------------------
__global__ __launch_bounds__(256) void k3_fused(const float* __restrict__ keys)
{
    __shared__ float qs[32][33];   // [token][k]
    __shared__ float ks[32][256];  // [k][key] transposed

    const int tid = threadIdx.x;
    const int tx = tid & 31;
    const int wy = tid >> 5;       // warp id: token group
    const int tt = blockIdx.x;
    const int h = blockIdx.y;
    const int t0 = tt * 32;

    ull acc[2][4][4];              // [p][token][key-pair-quad]
#pragma unroll
    for (int p = 0; p < 2; p++)
#pragma unroll
        for (int i = 0; i < 4; i++)
#pragma unroll
            for (int jq = 0; jq < 4; jq++) acc[p][i][jq] = 0ULL;

    const int tl = tid >> 3;
    const int kc = (tid & 7) << 2;

    for (int p = 0; p < 2; p++) {
        const float* qb = g_q + (size_t)(p * HV + h) * DHV;
        const float* kb = keys + ((size_t)(h * NKV + tid) * 2 + p) * DHV;
        for (int kt = 0; kt < DHV; kt += 32) {
            __syncthreads();
            float4 q4 = *(const float4*)(qb + (size_t)(t0 + tl) * QDV + kt + kc);
            qs[tl][kc + 0] = q4.x; qs[tl][kc + 1] = q4.y;
            qs[tl][kc + 2] = q4.z; qs[tl][kc + 3] = q4.w;
            const float* kr = kb + kt;  // key row n = tid (256 keys)
#pragma unroll
            for (int c = 0; c < 8; c++) {
                float4 k4 = *(const float4*)(kr + c * 4);
                ks[c * 4 + 0][tid] = k4.x; ks[c * 4 + 1][tid] = k4.y;
                ks[c * 4 + 2][tid] = k4.z; ks[c * 4 + 3][tid] = k4.w;
            }
            __syncthreads();
#pragma unroll 4
            for (int k = 0; k < 32; k++) {
                ull kv[4];
#pragma unroll
                for (int jq = 0; jq < 4; jq++)
                    kv[jq] = *(const ull*)&ks[k][64 * jq + 2 * tx];
#pragma unroll
                for (int i = 0; i < 4; i++) {
                    ull qd;
                    PACKDUP(qd, qs[wy + 8 * i][k]);
#pragma unroll
                    for (int jq = 0; jq < 4; jq++)
                        FMA2(acc[p][i][jq], qd, kv[jq]);
                }
            }
        }
    }

    // selection per token
#pragma unroll 1
    for (int i = 0; i < 4; i++) {
        const int t = t0 + wy + 8 * i;
        float s1s[2];
        int s1i[2];

        // stage 1: top-16 of 256 for BOTH p, interleaved (ILP-2)
        float v0[8], v1[8];
#pragma unroll
        for (int jq = 0; jq < 4; jq++) {
            unsigned lo, hi;
            UNPACK2(lo, hi, acc[0][i][jq]);
            v0[2 * jq + 0] = __uint_as_float(lo);
            v0[2 * jq + 1] = __uint_as_float(hi);
            UNPACK2(lo, hi, acc[1][i][jq]);
            v1[2 * jq + 0] = __uint_as_float(lo);
            v1[2 * jq + 1] = __uint_as_float(hi);
        }
        float os0 = 0.f, os1 = 0.f; int oi0 = 0, oi1 = 0;
#pragma unroll 1
        for (int it = 0; it < 16; it++) {
            float bv0 = -INFINITY, bv1 = -INFINITY;
            int bi0 = 0x7fffffff, bi1 = 0x7fffffff;
#pragma unroll
            for (int s = 0; s < 8; s++) {
                int n = ((s >> 1) << 6) + 2 * tx + (s & 1);
                if (v0[s] > bv0) { bv0 = v0[s]; bi0 = n; }
                if (v1[s] > bv1) { bv1 = v1[s]; bi1 = n; }
            }
#pragma unroll
            for (int o = 16; o; o >>= 1) {
                float ov0 = __shfl_xor_sync(0xffffffffu, bv0, o);
                int   on0 = __shfl_xor_sync(0xffffffffu, bi0, o);
                float ov1 = __shfl_xor_sync(0xffffffffu, bv1, o);
                int   on1 = __shfl_xor_sync(0xffffffffu, bi1, o);
                if (ov0 > bv0 || (ov0 == bv0 && on0 < bi0)) { bv0 = ov0; bi0 = on0; }
                if (ov1 > bv1 || (ov1 == bv1 && on1 < bi1)) { bv1 = ov1; bi1 = on1; }
            }
            if (tx == it) { os0 = bv0; oi0 = bi0; os1 = bv1; oi1 = bi1; }
            if (((bi0 >> 1) & 31) == tx) {
                int sl = ((bi0 >> 6) << 1) | (bi0 & 1);
                v0[sl] = -INFINITY;
            }
            if (((bi1 >> 1) & 31) == tx) {
                int sl = ((bi1 >> 6) << 1) | (bi1 & 1);
                v1[sl] = -INFINITY;
            }
        }
        s1s[0] = os0; s1i[0] = oi0;
        s1s[1] = os1; s1i[1] = oi1;

        // stage 2: top-16 of 50 pruned candidates (lane l: c=l and c=l+32)
        float v2[2]; int cc2[2];
#pragma unroll
        for (int e = 0; e < 2; e++) {
            int c = tx + 32 * e;
            int ii = c_ci[c], jj = c_cj[c];
            float sxv = __shfl_sync(0xffffffffu, s1s[0], ii);
            float syv = __shfl_sync(0xffffffffu, s1s[1], jj);
            v2[e] = (c < 50) ? sxv + syv : -INFINITY;
            cc2[e] = ii * 16 + jj;
        }
        float os = 0.f; int occ = 0;
#pragma unroll 1
        for (int it = 0; it < 16; it++) {
            float bv = -INFINITY; int bcc = 0x7fffffff;
#pragma unroll
            for (int e = 0; e < 2; e++)
                if (v2[e] > bv || (v2[e] == bv && cc2[e] < bcc)) { bv = v2[e]; bcc = cc2[e]; }
#pragma unroll
            for (int o = 16; o; o >>= 1) {
                float ov = __shfl_xor_sync(0xffffffffu, bv, o);
                int oc2 = __shfl_xor_sync(0xffffffffu, bcc, o);
                if (ov > bv || (ov == bv && oc2 < bcc)) { bv = ov; bcc = oc2; }
            }
            if (tx == it) { os = bv; occ = bcc; }
#pragma unroll
            for (int e = 0; e < 2; e++)
                if (cc2[e] == bcc) v2[e] = -INFINITY;
        }

        // softmax over 16 selected (lane 0 = max) + index gather
        float mx = __shfl_sync(0xffffffffu, os, 0);
        float ev = (tx < 16) ? expf(os - mx) : 0.f;
        float sum = ev;
#pragma unroll
        for (int o = 16; o; o >>= 1) sum += __shfl_xor_sync(0xffffffffu, sum, o);
        int ix = __shfl_sync(0xffffffffu, s1i[0], (occ >> 4) & 15);
        int iy = __shfl_sync(0xffffffffu, s1i[1], occ & 15);
        if (tx < 16) {
            int o = (t * HV + h) * KKV + tx;
            g_attn[o] = ev / sum;
            g_vidx[o] = ix * NKV + iy;
        }
    }
}

// ---------------------------------------------------------------------------
// K5: out[t,:] = sum_{m<128} attn[t,m] * values[vidx[t,m], :]
// (at DRAM/L2 bandwidth floor per ncu — unchanged)
// ---------------------------------------------------------------------------
__global__ __launch_bounds__(128) void k5_out(const float* __restrict__ values,
                                              float* __restrict__ out)
{
    __shared__ float sa[128];
    __shared__ int   sv[128];
    const int t = blockIdx.x;
    const int tid = threadIdx.x;
    sa[tid] = g_attn[(size_t)t * 128 + tid];
    sv[tid] = g_vidx[(size_t)t * 128 + tid];
    __syncthreads();

    const float4* V = (const float4*)values;
    float4 acc = make_float4(0.f, 0.f, 0.f, 0.f);
#pragma unroll 8
    for (int m = 0; m < 128; m++) {
        float a = sa[m];
        float4 vv = V[(size_t)sv[m] * 128 + tid];
        acc.x = fmaf(a, vv.x, acc.x);
        acc.y = fmaf(a, vv.y, acc.y);
        acc.z = fmaf(a, vv.z, acc.z);
        acc.w = fmaf(a, vv.w, acc.w);
    }
    ((float4*)out)[(size_t)t * 128 + tid] = acc;
}

// ---------------------------------------------------------------------------
extern "C" void kernel_launch(void* const* d_in, const int* in_sizes, int n_in,
                              void* d_out, int out_size)
{
    const float* x      = (const float*)d_in[0];  // (4,1024,512)
    const float* Wq     = (const float*)d_in[1];  // (2048,512)
    const float* ln_g   = (const float*)d_in[2];  // (128,)
    const float* ln_b   = (const float*)d_in[3];  // (128,)
    const float* keys   = (const float*)d_in[4];  // (8,256,2,128)
    const float* values = (const float*)d_in[5];  // (65536,512)
    float* out = (float*)d_out;                   // (4,1024,512)

    k1_gemm_ln<<<dim3(NTOKS / 64, QDV / 128), 256>>>(x, Wq, ln_g, ln_b);
    k3_fused<<<dim3(NTOKS / 32, HV), 256>>>(keys);
    k5_out<<<NTOKS, 128>>>(values, out);
}

// round 12
// speedup vs baseline: 1.1336x; 1.0354x over previous
#include <cuda_runtime.h>
#include <math.h>

// Problem constants
#define NTOKS 4096   // B*T
#define DIMV  512
#define QDV   2048   // 2*H*DH
#define HV    8
#define DHV   128
#define NKV   256
#define KKV   16

typedef unsigned long long ull;

// packed fp32x2 FMA (sm_103a FFMA2) — bit-exact fp32 per lane
#define FMA2(d, a, b) \
    asm("fma.rn.f32x2 %0, %1, %2, %0;" : "+l"(d) : "l"(a), "l"(b))
#define PACKDUP(out, x) \
    asm("mov.b64 %0, {%1, %1};" : "=l"(out) : "r"(__float_as_uint(x)))
#define UNPACK2(lo, hi, in) \
    asm("mov.b64 {%0, %1}, %2;" : "=r"(lo), "=r"(hi) : "l"(in))

// Scratch (allocation-free rule: __device__ globals)
__device__ __align__(16) float g_q[NTOKS * QDV];          // LN'd projected q
__device__ __align__(16) float g_attn[NTOKS * HV * KKV];  // softmax weights
__device__ __align__(16) int   g_vidx[NTOKS * HV * KKV];  // value row indices

// Stage-2 candidate tables: (i,j) with (i+1)(j+1) <= 16 — 50 candidates,
// provably a superset of the top-16 of sx[i]+sy[j] with sx,sy sorted desc
// (exact under the reference's lower-flattened-index tie-break).
__device__ __constant__ int c_ci[64] = {
    0,0,0,0,0,0,0,0,0,0,0,0,0,0,0,0,
    1,1,1,1,1,1,1,1,
    2,2,2,2,2,
    3,3,3,3,
    4,4,4,
    5,5, 6,6, 7,7,
    8,9,10,11,12,13,14,15,
    0,0,0,0,0,0,0,0,0,0,0,0,0,0};
__device__ __constant__ int c_cj[64] = {
    0,1,2,3,4,5,6,7,8,9,10,11,12,13,14,15,
    0,1,2,3,4,5,6,7,
    0,1,2,3,4,
    0,1,2,3,
    0,1,2,
    0,1, 0,1, 0,1,
    0,0,0,0,0,0,0,0,
    0,0,0,0,0,0,0,0,0,0,0,0,0,0};

// ---------------------------------------------------------------------------
// K1 (+fused LN): VERBATIM round 11 (583.6us). q = LN(x @ Wq^T), FFMA2,
// bit-exact sequential-k chain, register-prefetch pipeline, k2-layout LN.
// ---------------------------------------------------------------------------
__global__ __launch_bounds__(256) void k1_gemm_ln(const float* __restrict__ X,
                                                  const float* __restrict__ W,
                                                  const float* __restrict__ gamma,
                                                  const float* __restrict__ beta)
{
    __shared__ float As[16][68];    // [k][m] 64 rows + pad
    __shared__ float Bs[16][132];   // [k][n] 128 rows + pad

    const int tid = threadIdx.x;
    const int tx = tid & 31;       // n-group: cols tx*4..tx*4+3
    const int ty = tid >> 5;       // m-group (warp id)
    const int m0 = blockIdx.x * 64;
    const int n0 = blockIdx.y * 128;   // exactly one (p,h) head slice

    ull acc[4][4];                 // [row-pair][col]
#pragma unroll
    for (int ip = 0; ip < 4; ip++)
#pragma unroll
        for (int j = 0; j < 4; j++) acc[ip][j] = 0ULL;

    const int arow = tid >> 2;          // 0..63
    const int akc  = (tid & 3) << 2;    // 0,4,8,12
    const int brow0 = tid >> 2;         // 0..63   (q=0)
    const int brow1 = 64 + (tid >> 2);  // 64..127 (q=1)

    const float* Abase = X + (size_t)(m0 + arow) * DIMV + akc;
    const float* Bbase0 = W + (size_t)(n0 + brow0) * DIMV + akc;
    const float* Bbase1 = W + (size_t)(n0 + brow1) * DIMV + akc;

    // prologue: prefetch tile kt=0
    float4 pa  = *(const float4*)(Abase);
    float4 pb0 = *(const float4*)(Bbase0);
    float4 pb1 = *(const float4*)(Bbase1);

    for (int kt = 0; kt < DIMV; kt += 16) {
        As[akc + 0][arow] = pa.x; As[akc + 1][arow] = pa.y;
        As[akc + 2][arow] = pa.z; As[akc + 3][arow] = pa.w;
        Bs[akc + 0][brow0] = pb0.x; Bs[akc + 1][brow0] = pb0.y;
        Bs[akc + 2][brow0] = pb0.z; Bs[akc + 3][brow0] = pb0.w;
        Bs[akc + 0][brow1] = pb1.x; Bs[akc + 1][brow1] = pb1.y;
        Bs[akc + 2][brow1] = pb1.z; Bs[akc + 3][brow1] = pb1.w;
        __syncthreads();

        if (kt + 16 < DIMV) {
            pa  = *(const float4*)(Abase + kt + 16);
            pb0 = *(const float4*)(Bbase0 + kt + 16);
            pb1 = *(const float4*)(Bbase1 + kt + 16);
        }

#pragma unroll 4
        for (int k = 0; k < 16; k++) {
            ulonglong2 a01 = *(const ulonglong2*)&As[k][ty * 4];
            ulonglong2 a23 = *(const ulonglong2*)&As[k][32 + ty * 4];
            ull av[4] = {a01.x, a01.y, a23.x, a23.y};
            float4 b = *(const float4*)&Bs[k][tx * 4];
            ull bd[4];
            PACKDUP(bd[0], b.x); PACKDUP(bd[1], b.y);
            PACKDUP(bd[2], b.z); PACKDUP(bd[3], b.w);
#pragma unroll
            for (int ip = 0; ip < 4; ip++)
#pragma unroll
                for (int j = 0; j < 4; j++)
                    FMA2(acc[ip][j], av[ip], bd[j]);
        }
        __syncthreads();
    }

    // epilogue: LN per row (exact k2 layout + reduction tree), then store.
    float4 g4 = *(const float4*)(gamma + tx * 4);
    float4 b4 = *(const float4*)(beta + tx * 4);

#pragma unroll
    for (int ip = 0; ip < 4; ip++) {
#pragma unroll
        for (int e = 0; e < 2; e++) {
            int row = (ip >> 1) * 32 + ty * 4 + (ip & 1) * 2 + e;
            float4 v;
            {
                unsigned lo, hi;
                UNPACK2(lo, hi, acc[ip][0]); v.x = __uint_as_float(e ? hi : lo);
                UNPACK2(lo, hi, acc[ip][1]); v.y = __uint_as_float(e ? hi : lo);
                UNPACK2(lo, hi, acc[ip][2]); v.z = __uint_as_float(e ? hi : lo);
                UNPACK2(lo, hi, acc[ip][3]); v.w = __uint_as_float(e ? hi : lo);
            }
            float s = v.x + v.y + v.z + v.w;
#pragma unroll
            for (int o = 16; o; o >>= 1) s += __shfl_xor_sync(0xffffffffu, s, o);
            float mu = s * (1.0f / 128.0f);

            float dx = v.x - mu, dy = v.y - mu, dz = v.z - mu, dw = v.w - mu;
            float ss = dx * dx + dy * dy + dz * dz + dw * dw;
#pragma unroll
            for (int o = 16; o; o >>= 1) ss += __shfl_xor_sync(0xffffffffu, ss, o);
            float inv = rsqrtf(ss * (1.0f / 128.0f) + 1e-5f);

            v.x = dx * inv * g4.x + b4.x;
            v.y = dy * inv * g4.y + b4.y;
            v.z = dz * inv * g4.z + b4.z;
            v.w = dw * inv * g4.w + b4.w;
            float* dst = g_q + (size_t)(m0 + row) * QDV + n0 + tx * 4;
            *(float4*)dst = v;
        }
    }
}

// ---------------------------------------------------------------------------
// K3 (fused K4), p-SEQUENTIAL: dots-p0 -> stage-1-p0 -> dots-p1 (acc reuse)
// -> stage-1-p1 -> stage-2 -> softmax. Halves accumulator registers (32 ull
// -> 16 ull) so 3 CTAs/SM fit. Per-chain FMA order (k=0..127 per (p,key))
// and all selection semantics unchanged. Stage-1 ILP-2 now over token pairs.
// ---------------------------------------------------------------------------
__global__ __launch_bounds__(256, 3) void k3_fused(const float* __restrict__ keys)
{
    __shared__ float qs[32][33];   // [token][k]
    __shared__ float ks[32][256];  // [k][key] transposed

    const int tid = threadIdx.x;
    const int tx = tid & 31;
    const int wy = tid >> 5;       // warp id: token group
    const int tt = blockIdx.x;
    const int h = blockIdx.y;
    const int t0 = tt * 32;

    const int tl = tid >> 3;
    const int kc = (tid & 7) << 2;

    float s1s0[4], s1s1[4];        // stage-1 results per token per p
    int   s1i0[4], s1i1[4];

#pragma unroll 1
    for (int p = 0; p < 2; p++) {
        ull acc[4][4];             // [token][key-pair-quad] — reused across p
#pragma unroll
        for (int i = 0; i < 4; i++)
#pragma unroll
            for (int jq = 0; jq < 4; jq++) acc[i][jq] = 0ULL;

        const float* qb = g_q + (size_t)(p * HV + h) * DHV;
        const float* kb = keys + ((size_t)(h * NKV + tid) * 2 + p) * DHV;
        for (int kt = 0; kt < DHV; kt += 32) {
            __syncthreads();
            float4 q4 = *(const float4*)(qb + (size_t)(t0 + tl) * QDV + kt + kc);
            qs[tl][kc + 0] = q4.x; qs[tl][kc + 1] = q4.y;
            qs[tl][kc + 2] = q4.z; qs[tl][kc + 3] = q4.w;
            const float* kr = kb + kt;  // key row n = tid (256 keys)
#pragma unroll
            for (int c = 0; c < 8; c++) {
                float4 k4 = *(const float4*)(kr + c * 4);
                ks[c * 4 + 0][tid] = k4.x; ks[c * 4 + 1][tid] = k4.y;
                ks[c * 4 + 2][tid] = k4.z; ks[c * 4 + 3][tid] = k4.w;
            }
            __syncthreads();
#pragma unroll 4
            for (int k = 0; k < 32; k++) {
                ull kv[4];
#pragma unroll
                for (int jq = 0; jq < 4; jq++)
                    kv[jq] = *(const ull*)&ks[k][64 * jq + 2 * tx];
#pragma unroll
                for (int i = 0; i < 4; i++) {
                    ull qd;
                    PACKDUP(qd, qs[wy + 8 * i][k]);
#pragma unroll
                    for (int jq = 0; jq < 4; jq++)
                        FMA2(acc[i][jq], qd, kv[jq]);
                }
            }
        }

        // stage-1 for this p: top-16 of 256 per token, token pairs ILP-2.
        // Per-token op sequence and tie-breaks identical to prior rounds.
#pragma unroll
        for (int ii = 0; ii < 4; ii += 2) {
            float va[8], vb[8];
#pragma unroll
            for (int jq = 0; jq < 4; jq++) {
                unsigned lo, hi;
                UNPACK2(lo, hi, acc[ii][jq]);
                va[2 * jq + 0] = __uint_as_float(lo);
                va[2 * jq + 1] = __uint_as_float(hi);
                UNPACK2(lo, hi, acc[ii + 1][jq]);
                vb[2 * jq + 0] = __uint_as_float(lo);
                vb[2 * jq + 1] = __uint_as_float(hi);
            }
            float osa = 0.f, osb = 0.f; int oia = 0, oib = 0;
#pragma unroll 1
            for (int it = 0; it < 16; it++) {
                float bva = -INFINITY, bvb = -INFINITY;
                int bia = 0x7fffffff, bib = 0x7fffffff;
#pragma unroll
                for (int s = 0; s < 8; s++) {
                    int n = ((s >> 1) << 6) + 2 * tx + (s & 1);
                    if (va[s] > bva) { bva = va[s]; bia = n; }
                    if (vb[s] > bvb) { bvb = vb[s]; bib = n; }
                }
#pragma unroll
                for (int o = 16; o; o >>= 1) {
                    float ova = __shfl_xor_sync(0xffffffffu, bva, o);
                    int   ona = __shfl_xor_sync(0xffffffffu, bia, o);
                    float ovb = __shfl_xor_sync(0xffffffffu, bvb, o);
                    int   onb = __shfl_xor_sync(0xffffffffu, bib, o);
                    if (ova > bva || (ova == bva && ona < bia)) { bva = ova; bia = ona; }
                    if (ovb > bvb || (ovb == bvb && onb < bib)) { bvb = ovb; bib = onb; }
                }
                if (tx == it) { osa = bva; oia = bia; osb = bvb; oib = bib; }
                if (((bia >> 1) & 31) == tx) {
                    int sl = ((bia >> 6) << 1) | (bia & 1);
                    va[sl] = -INFINITY;
                }
                if (((bib >> 1) & 31) == tx) {
                    int sl = ((bib >> 6) << 1) | (bib & 1);
                    vb[sl] = -INFINITY;
                }
            }
            if (p == 0) {
                s1s0[ii] = osa; s1i0[ii] = oia;
                s1s0[ii + 1] = osb; s1i0[ii + 1] = oib;
            } else {
                s1s1[ii] = osa; s1i1[ii] = oia;
                s1s1[ii + 1] = osb; s1i1[ii + 1] = oib;
            }
        }
    }

    // stage-2 + softmax per token (verbatim logic from round 9)
#pragma unroll
    for (int i = 0; i < 4; i++) {
        const int t = t0 + wy + 8 * i;
        float sx = s1s0[i], sy = s1s1[i];
        int ixr = s1i0[i], iyr = s1i1[i];

        float v2[2]; int cc2[2];
#pragma unroll
        for (int e = 0; e < 2; e++) {
            int c = tx + 32 * e;
            int ii = c_ci[c], jj = c_cj[c];
            float sxv = __shfl_sync(0xffffffffu, sx, ii);
            float syv = __shfl_sync(0xffffffffu, sy, jj);
            v2[e] = (c < 50) ? sxv + syv : -INFINITY;
            cc2[e] = ii * 16 + jj;
        }
        float os = 0.f; int occ = 0;
#pragma unroll 1
        for (int it = 0; it < 16; it++) {
            float bv = -INFINITY; int bcc = 0x7fffffff;
#pragma unroll
            for (int e = 0; e < 2; e++)
                if (v2[e] > bv || (v2[e] == bv && cc2[e] < bcc)) { bv = v2[e]; bcc = cc2[e]; }
#pragma unroll
            for (int o = 16; o; o >>= 1) {
                float ov = __shfl_xor_sync(0xffffffffu, bv, o);
                int oc2 = __shfl_xor_sync(0xffffffffu, bcc, o);
                if (ov > bv || (ov == bv && oc2 < bcc)) { bv = ov; bcc = oc2; }
            }
            if (tx == it) { os = bv; occ = bcc; }
#pragma unroll
            for (int e = 0; e < 2; e++)
                if (cc2[e] == bcc) v2[e] = -INFINITY;
        }

        // softmax over 16 selected (lane 0 = max) + index gather
        float mx = __shfl_sync(0xffffffffu, os, 0);
        float ev = (tx < 16) ? expf(os - mx) : 0.f;
        float sum = ev;
#pragma unroll
        for (int o = 16; o; o >>= 1) sum += __shfl_xor_sync(0xffffffffu, sum, o);
        int ix = __shfl_sync(0xffffffffu, ixr, (occ >> 4) & 15);
        int iy = __shfl_sync(0xffffffffu, iyr, occ & 15);
        if (tx < 16) {
            int o = (t * HV + h) * KKV + tx;
            g_attn[o] = ev / sum;
            g_vidx[o] = ix * NKV + iy;
        }
    }
}

// ---------------------------------------------------------------------------
// K5: out[t,:] = sum_{m<128} attn[t,m] * values[vidx[t,m], :]
// (at DRAM/L2 bandwidth floor per ncu — unchanged)
// ---------------------------------------------------------------------------
__global__ __launch_bounds__(128) void k5_out(const float* __restrict__ values,
                                              float* __restrict__ out)
{
    __shared__ float sa[128];
    __shared__ int   sv[128];
    const int t = blockIdx.x;
    const int tid = threadIdx.x;
    sa[tid] = g_attn[(size_t)t * 128 + tid];
    sv[tid] = g_vidx[(size_t)t * 128 + tid];
    __syncthreads();

    const float4* V = (const float4*)values;
    float4 acc = make_float4(0.f, 0.f, 0.f, 0.f);
#pragma unroll 8
    for (int m = 0; m < 128; m++) {
        float a = sa[m];
        float4 vv = V[(size_t)sv[m] * 128 + tid];
        acc.x = fmaf(a, vv.x, acc.x);
        acc.y = fmaf(a, vv.y, acc.y);
        acc.z = fmaf(a, vv.z, acc.z);
        acc.w = fmaf(a, vv.w, acc.w);
    }
    ((float4*)out)[(size_t)t * 128 + tid] = acc;
}

// ---------------------------------------------------------------------------
extern "C" void kernel_launch(void* const* d_in, const int* in_sizes, int n_in,
                              void* d_out, int out_size)
{
    const float* x      = (const float*)d_in[0];  // (4,1024,512)
    const float* Wq     = (const float*)d_in[1];  // (2048,512)
    const float* ln_g   = (const float*)d_in[2];  // (128,)
    const float* ln_b   = (const float*)d_in[3];  // (128,)
    const float* keys   = (const float*)d_in[4];  // (8,256,2,128)
    const float* values = (const float*)d_in[5];  // (65536,512)
    float* out = (float*)d_out;                   // (4,1024,512)

    k1_gemm_ln<<<dim3(NTOKS / 64, QDV / 128), 256>>>(x, Wq, ln_g, ln_b);
    k3_fused<<<dim3(NTOKS / 32, HV), 256>>>(keys);
    k5_out<<<NTOKS, 128>>>(values, out);
}

// round 13
// speedup vs baseline: 1.1807x; 1.0416x over previous
#include <cuda_runtime.h>
#include <math.h>

// Problem constants
#define NTOKS 4096   // B*T
#define DIMV  512
#define QDV   2048   // 2*H*DH
#define HV    8
#define DHV   128
#define NKV   256
#define KKV   16

typedef unsigned long long ull;

// packed fp32x2 FMA (sm_103a FFMA2) — bit-exact fp32 per lane
#define FMA2(d, a, b) \
    asm("fma.rn.f32x2 %0, %1, %2, %0;" : "+l"(d) : "l"(a), "l"(b))
#define PACKDUP(out, x) \
    asm("mov.b64 %0, {%1, %1};" : "=l"(out) : "r"(__float_as_uint(x)))
#define UNPACK2(lo, hi, in) \
    asm("mov.b64 {%0, %1}, %2;" : "=r"(lo), "=r"(hi) : "l"(in))

// Scratch (allocation-free rule: __device__ globals)
__device__ __align__(16) float g_q[NTOKS * QDV];          // LN'd projected q
__device__ __align__(16) float g_attn[NTOKS * HV * KKV];  // softmax weights
__device__ __align__(16) int   g_vidx[NTOKS * HV * KKV];  // value row indices

// Stage-2 candidate tables: (i,j) with (i+1)(j+1) <= 16 — 50 candidates,
// provably a superset of the top-16 of sx[i]+sy[j] with sx,sy sorted desc
// (exact under the reference's lower-flattened-index tie-break).
__device__ __constant__ int c_ci[64] = {
    0,0,0,0,0,0,0,0,0,0,0,0,0,0,0,0,
    1,1,1,1,1,1,1,1,
    2,2,2,2,2,
    3,3,3,3,
    4,4,4,
    5,5, 6,6, 7,7,
    8,9,10,11,12,13,14,15,
    0,0,0,0,0,0,0,0,0,0,0,0,0,0};
__device__ __constant__ int c_cj[64] = {
    0,1,2,3,4,5,6,7,8,9,10,11,12,13,14,15,
    0,1,2,3,4,5,6,7,
    0,1,2,3,4,
    0,1,2,3,
    0,1,2,
    0,1, 0,1, 0,1,
    0,0,0,0,0,0,0,0,
    0,0,0,0,0,0,0,0,0,0,0,0,0,0};

// ---------------------------------------------------------------------------
// K1 (+fused LN): VERBATIM round 12 (563.7us). q = LN(x @ Wq^T), FFMA2,
// bit-exact sequential-k chain, register-prefetch pipeline, k2-layout LN.
// ---------------------------------------------------------------------------
__global__ __launch_bounds__(256) void k1_gemm_ln(const float* __restrict__ X,
                                                  const float* __restrict__ W,
                                                  const float* __restrict__ gamma,
                                                  const float* __restrict__ beta)
{
    __shared__ float As[16][68];    // [k][m] 64 rows + pad
    __shared__ float Bs[16][132];   // [k][n] 128 rows + pad

    const int tid = threadIdx.x;
    const int tx = tid & 31;       // n-group: cols tx*4..tx*4+3
    const int ty = tid >> 5;       // m-group (warp id)
    const int m0 = blockIdx.x * 64;
    const int n0 = blockIdx.y * 128;   // exactly one (p,h) head slice

    ull acc[4][4];                 // [row-pair][col]
#pragma unroll
    for (int ip = 0; ip < 4; ip++)
#pragma unroll
        for (int j = 0; j < 4; j++) acc[ip][j] = 0ULL;

    const int arow = tid >> 2;          // 0..63
    const int akc  = (tid & 3) << 2;    // 0,4,8,12
    const int brow0 = tid >> 2;         // 0..63   (q=0)
    const int brow1 = 64 + (tid >> 2);  // 64..127 (q=1)

    const float* Abase = X + (size_t)(m0 + arow) * DIMV + akc;
    const float* Bbase0 = W + (size_t)(n0 + brow0) * DIMV + akc;
    const float* Bbase1 = W + (size_t)(n0 + brow1) * DIMV + akc;

    // prologue: prefetch tile kt=0
    float4 pa  = *(const float4*)(Abase);
    float4 pb0 = *(const float4*)(Bbase0);
    float4 pb1 = *(const float4*)(Bbase1);

    for (int kt = 0; kt < DIMV; kt += 16) {
        As[akc + 0][arow] = pa.x; As[akc + 1][arow] = pa.y;
        As[akc + 2][arow] = pa.z; As[akc + 3][arow] = pa.w;
        Bs[akc + 0][brow0] = pb0.x; Bs[akc + 1][brow0] = pb0.y;
        Bs[akc + 2][brow0] = pb0.z; Bs[akc + 3][brow0] = pb0.w;
        Bs[akc + 0][brow1] = pb1.x; Bs[akc + 1][brow1] = pb1.y;
        Bs[akc + 2][brow1] = pb1.z; Bs[akc + 3][brow1] = pb1.w;
        __syncthreads();

        if (kt + 16 < DIMV) {
            pa  = *(const float4*)(Abase + kt + 16);
            pb0 = *(const float4*)(Bbase0 + kt + 16);
            pb1 = *(const float4*)(Bbase1 + kt + 16);
        }

#pragma unroll 4
        for (int k = 0; k < 16; k++) {
            ulonglong2 a01 = *(const ulonglong2*)&As[k][ty * 4];
            ulonglong2 a23 = *(const ulonglong2*)&As[k][32 + ty * 4];
            ull av[4] = {a01.x, a01.y, a23.x, a23.y};
            float4 b = *(const float4*)&Bs[k][tx * 4];
            ull bd[4];
            PACKDUP(bd[0], b.x); PACKDUP(bd[1], b.y);
            PACKDUP(bd[2], b.z); PACKDUP(bd[3], b.w);
#pragma unroll
            for (int ip = 0; ip < 4; ip++)
#pragma unroll
                for (int j = 0; j < 4; j++)
                    FMA2(acc[ip][j], av[ip], bd[j]);
        }
        __syncthreads();
    }

    // epilogue: LN per row (exact k2 layout + reduction tree), then store.
    float4 g4 = *(const float4*)(gamma + tx * 4);
    float4 b4 = *(const float4*)(beta + tx * 4);

#pragma unroll
    for (int ip = 0; ip < 4; ip++) {
#pragma unroll
        for (int e = 0; e < 2; e++) {
            int row = (ip >> 1) * 32 + ty * 4 + (ip & 1) * 2 + e;
            float4 v;
            {
                unsigned lo, hi;
                UNPACK2(lo, hi, acc[ip][0]); v.x = __uint_as_float(e ? hi : lo);
                UNPACK2(lo, hi, acc[ip][1]); v.y = __uint_as_float(e ? hi : lo);
                UNPACK2(lo, hi, acc[ip][2]); v.z = __uint_as_float(e ? hi : lo);
                UNPACK2(lo, hi, acc[ip][3]); v.w = __uint_as_float(e ? hi : lo);
            }
            float s = v.x + v.y + v.z + v.w;
#pragma unroll
            for (int o = 16; o; o >>= 1) s += __shfl_xor_sync(0xffffffffu, s, o);
            float mu = s * (1.0f / 128.0f);

            float dx = v.x - mu, dy = v.y - mu, dz = v.z - mu, dw = v.w - mu;
            float ss = dx * dx + dy * dy + dz * dz + dw * dw;
#pragma unroll
            for (int o = 16; o; o >>= 1) ss += __shfl_xor_sync(0xffffffffu, ss, o);
            float inv = rsqrtf(ss * (1.0f / 128.0f) + 1e-5f);

            v.x = dx * inv * g4.x + b4.x;
            v.y = dy * inv * g4.y + b4.y;
            v.z = dz * inv * g4.z + b4.z;
            v.w = dw * inv * g4.w + b4.w;
            float* dst = g_q + (size_t)(m0 + row) * QDV + n0 + tx * 4;
            *(float4*)dst = v;
        }
    }
}

// ---------------------------------------------------------------------------
// K3 (fused K4), p-sequential dots (verbatim round 12) + selection with
// ILP-4: all 4 tokens' dependent shuffle chains interleaved in stage-1
// (per p), stage-2, and softmax. Per-token op order and tie-breaks are
// unchanged — only cross-token interleaving (independent data).
// ---------------------------------------------------------------------------
__global__ __launch_bounds__(256, 3) void k3_fused(const float* __restrict__ keys)
{
    __shared__ float qs[32][33];   // [token][k]
    __shared__ float ks[32][256];  // [k][key] transposed

    const int tid = threadIdx.x;
    const int tx = tid & 31;
    const int wy = tid >> 5;       // warp id: token group
    const int tt = blockIdx.x;
    const int h = blockIdx.y;
    const int t0 = tt * 32;

    const int tl = tid >> 3;
    const int kc = (tid & 7) << 2;

    float s1s0[4], s1s1[4];        // stage-1 results per token per p
    int   s1i0[4], s1i1[4];

#pragma unroll 1
    for (int p = 0; p < 2; p++) {
        ull acc[4][4];             // [token][key-pair-quad] — reused across p
#pragma unroll
        for (int i = 0; i < 4; i++)
#pragma unroll
            for (int jq = 0; jq < 4; jq++) acc[i][jq] = 0ULL;

        const float* qb = g_q + (size_t)(p * HV + h) * DHV;
        const float* kb = keys + ((size_t)(h * NKV + tid) * 2 + p) * DHV;
        for (int kt = 0; kt < DHV; kt += 32) {
            __syncthreads();
            float4 q4 = *(const float4*)(qb + (size_t)(t0 + tl) * QDV + kt + kc);
            qs[tl][kc + 0] = q4.x; qs[tl][kc + 1] = q4.y;
            qs[tl][kc + 2] = q4.z; qs[tl][kc + 3] = q4.w;
            const float* kr = kb + kt;  // key row n = tid (256 keys)
#pragma unroll
            for (int c = 0; c < 8; c++) {
                float4 k4 = *(const float4*)(kr + c * 4);
                ks[c * 4 + 0][tid] = k4.x; ks[c * 4 + 1][tid] = k4.y;
                ks[c * 4 + 2][tid] = k4.z; ks[c * 4 + 3][tid] = k4.w;
            }
            __syncthreads();
#pragma unroll 4
            for (int k = 0; k < 32; k++) {
                ull kv[4];
#pragma unroll
                for (int jq = 0; jq < 4; jq++)
                    kv[jq] = *(const ull*)&ks[k][64 * jq + 2 * tx];
#pragma unroll
                for (int i = 0; i < 4; i++) {
                    ull qd;
                    PACKDUP(qd, qs[wy + 8 * i][k]);
#pragma unroll
                    for (int jq = 0; jq < 4; jq++)
                        FMA2(acc[i][jq], qd, kv[jq]);
                }
            }
        }

        // stage-1 for this p: top-16 of 256 per token, ALL 4 tokens ILP.
        float v[4][8];
#pragma unroll
        for (int i = 0; i < 4; i++)
#pragma unroll
            for (int jq = 0; jq < 4; jq++) {
                unsigned lo, hi;
                UNPACK2(lo, hi, acc[i][jq]);
                v[i][2 * jq + 0] = __uint_as_float(lo);
                v[i][2 * jq + 1] = __uint_as_float(hi);
            }
        float osr[4]; int oir[4];
#pragma unroll
        for (int i = 0; i < 4; i++) { osr[i] = 0.f; oir[i] = 0; }
#pragma unroll 1
        for (int it = 0; it < 16; it++) {
            float bv[4]; int bi[4];
#pragma unroll
            for (int i = 0; i < 4; i++) { bv[i] = -INFINITY; bi[i] = 0x7fffffff; }
#pragma unroll
            for (int s = 0; s < 8; s++) {
                int n = ((s >> 1) << 6) + 2 * tx + (s & 1);
#pragma unroll
                for (int i = 0; i < 4; i++)
                    if (v[i][s] > bv[i]) { bv[i] = v[i][s]; bi[i] = n; }
            }
#pragma unroll
            for (int o = 16; o; o >>= 1) {
#pragma unroll
                for (int i = 0; i < 4; i++) {
                    float ov = __shfl_xor_sync(0xffffffffu, bv[i], o);
                    int   on = __shfl_xor_sync(0xffffffffu, bi[i], o);
                    if (ov > bv[i] || (ov == bv[i] && on < bi[i])) { bv[i] = ov; bi[i] = on; }
                }
            }
#pragma unroll
            for (int i = 0; i < 4; i++) {
                if (tx == it) { osr[i] = bv[i]; oir[i] = bi[i]; }
                if (((bi[i] >> 1) & 31) == tx) {
                    int sl = ((bi[i] >> 6) << 1) | (bi[i] & 1);
                    v[i][sl] = -INFINITY;
                }
            }
        }
#pragma unroll
        for (int i = 0; i < 4; i++) {
            if (p == 0) { s1s0[i] = osr[i]; s1i0[i] = oir[i]; }
            else        { s1s1[i] = osr[i]; s1i1[i] = oir[i]; }
        }
    }

    // stage-2: top-16 of 50 pruned candidates, ALL 4 tokens ILP.
    float v2[4][2];
    int cc2[2];                    // candidate ids identical for all tokens
#pragma unroll
    for (int e = 0; e < 2; e++) {
        int c = tx + 32 * e;
        int ii = c_ci[c], jj = c_cj[c];
        cc2[e] = ii * 16 + jj;
#pragma unroll
        for (int i = 0; i < 4; i++) {
            float sxv = __shfl_sync(0xffffffffu, s1s0[i], ii);
            float syv = __shfl_sync(0xffffffffu, s1s1[i], jj);
            v2[i][e] = (c < 50) ? sxv + syv : -INFINITY;
        }
    }
    float os[4]; int occ[4];
#pragma unroll
    for (int i = 0; i < 4; i++) { os[i] = 0.f; occ[i] = 0; }
#pragma unroll 1
    for (int it = 0; it < 16; it++) {
        float bv[4]; int bcc[4];
#pragma unroll
        for (int i = 0; i < 4; i++) { bv[i] = -INFINITY; bcc[i] = 0x7fffffff; }
#pragma unroll
        for (int e = 0; e < 2; e++)
#pragma unroll
            for (int i = 0; i < 4; i++)
                if (v2[i][e] > bv[i] || (v2[i][e] == bv[i] && cc2[e] < bcc[i])) {
                    bv[i] = v2[i][e]; bcc[i] = cc2[e];
                }
#pragma unroll
        for (int o = 16; o; o >>= 1) {
#pragma unroll
            for (int i = 0; i < 4; i++) {
                float ov = __shfl_xor_sync(0xffffffffu, bv[i], o);
                int   oc = __shfl_xor_sync(0xffffffffu, bcc[i], o);
                if (ov > bv[i] || (ov == bv[i] && oc < bcc[i])) { bv[i] = ov; bcc[i] = oc; }
            }
        }
#pragma unroll
        for (int i = 0; i < 4; i++) {
            if (tx == it) { os[i] = bv[i]; occ[i] = bcc[i]; }
#pragma unroll
            for (int e = 0; e < 2; e++)
                if (cc2[e] == bcc[i]) v2[i][e] = -INFINITY;
        }
    }

    // softmax over 16 selected (lane 0 = max) + index gather, ILP-4.
    float ev[4], sum[4];
#pragma unroll
    for (int i = 0; i < 4; i++) {
        float mx = __shfl_sync(0xffffffffu, os[i], 0);
        ev[i] = (tx < 16) ? expf(os[i] - mx) : 0.f;
        sum[i] = ev[i];
    }
#pragma unroll
    for (int o = 16; o; o >>= 1)
#pragma unroll
        for (int i = 0; i < 4; i++)
            sum[i] += __shfl_xor_sync(0xffffffffu, sum[i], o);
#pragma unroll
    for (int i = 0; i < 4; i++) {
        int ix = __shfl_sync(0xffffffffu, s1i0[i], (occ[i] >> 4) & 15);
        int iy = __shfl_sync(0xffffffffu, s1i1[i], occ[i] & 15);
        if (tx < 16) {
            const int t = t0 + wy + 8 * i;
            int o = (t * HV + h) * KKV + tx;
            g_attn[o] = ev[i] / sum[i];
            g_vidx[o] = ix * NKV + iy;
        }
    }
}

// ---------------------------------------------------------------------------
// K5: out[t,:] = sum_{m<128} attn[t,m] * values[vidx[t,m], :]
// (at DRAM/L2 bandwidth floor per ncu — unchanged)
// ---------------------------------------------------------------------------
__global__ __launch_bounds__(128) void k5_out(const float* __restrict__ values,
                                              float* __restrict__ out)
{
    __shared__ float sa[128];
    __shared__ int   sv[128];
    const int t = blockIdx.x;
    const int tid = threadIdx.x;
    sa[tid] = g_attn[(size_t)t * 128 + tid];
    sv[tid] = g_vidx[(size_t)t * 128 + tid];
    __syncthreads();

    const float4* V = (const float4*)values;
    float4 acc = make_float4(0.f, 0.f, 0.f, 0.f);
#pragma unroll 8
    for (int m = 0; m < 128; m++) {
        float a = sa[m];
        float4 vv = V[(size_t)sv[m] * 128 + tid];
        acc.x = fmaf(a, vv.x, acc.x);
        acc.y = fmaf(a, vv.y, acc.y);
        acc.z = fmaf(a, vv.z, acc.z);
        acc.w = fmaf(a, vv.w, acc.w);
    }
    ((float4*)out)[(size_t)t * 128 + tid] = acc;
}

// ---------------------------------------------------------------------------
extern "C" void kernel_launch(void* const* d_in, const int* in_sizes, int n_in,
                              void* d_out, int out_size)
{
    const float* x      = (const float*)d_in[0];  // (4,1024,512)
    const float* Wq     = (const float*)d_in[1];  // (2048,512)
    const float* ln_g   = (const float*)d_in[2];  // (128,)
    const float* ln_b   = (const float*)d_in[3];  // (128,)
    const float* keys   = (const float*)d_in[4];  // (8,256,2,128)
    const float* values = (const float*)d_in[5];  // (65536,512)
    float* out = (float*)d_out;                   // (4,1024,512)

    k1_gemm_ln<<<dim3(NTOKS / 64, QDV / 128), 256>>>(x, Wq, ln_g, ln_b);
    k3_fused<<<dim3(NTOKS / 32, HV), 256>>>(keys);
    k5_out<<<NTOKS, 128>>>(values, out);
}